// round 15
// baseline (speedup 1.0000x reference)
#include <cuda_runtime.h>
#include <cuda_fp16.h>
#include <cstdint>

#define KDIM 512
#define S_N 50000
#define EN 6
#define NEG 0.2f
#define NE3 150000

// ---------------- scratch (static __device__, no allocation) ----------------
__device__ float g_wa[4][2][KDIM];      // W_g @ a_src / a_dst
__device__ float g_he[4][EN][KDIM];     // exer_emb @ W_g
__device__ float g_ase[4][EN];          // h_e . a_src
__device__ float g_ade[4][EN];          // h_e . a_dst
__device__ float g_as2[S_N], g_ad2[S_N], g_as3[S_N];
__device__ float g_as0[KDIM], g_ad0[KDIM], g_as1[KDIM];
__device__ float g_den1[EN], g_den3[EN];
__device__ float g_agg1[EN*KDIM], g_agg3[EN*KDIM];
__device__ float g_B[EN*KDIM], g_C[EN*KDIM];
// counters: g_cA zeroed by phaseC's exer (prev replay) / static init;
// g_c1/g_c3/g_cbc zeroed by launch-1's init block (ordered before phaseC).
__device__ int g_cA, g_c1, g_c3, g_cbc;

// fp16 operands for the tensor-core student GEMM
__device__ __half g_Ah[(size_t)S_N*KDIM];
__device__ __half g_Wh[KDIM*KDIM];   // W2^T: [n][k]

__device__ __forceinline__ float lrelu(float x){ return x > 0.f ? x : NEG*x; }

// ---------------- PTX helpers (all legal on plain compute_103) ----------------
__device__ __forceinline__ uint32_t smem_u32(const void* p){
    uint32_t a;
    asm("{ .reg .u64 t; cvta.to.shared.u64 t, %1; cvt.u32.u64 %0, t; }" : "=r"(a) : "l"(p));
    return a;
}
__device__ __forceinline__ void cpa16(uint32_t s, const void* g){
    asm volatile("cp.async.cg.shared.global [%0], [%1], 16;" :: "r"(s), "l"(g));
}
#define CPA_COMMIT() asm volatile("cp.async.commit_group;" ::: "memory")
#define CPA_WAIT(n)  asm volatile("cp.async.wait_group %0;" :: "n"(n) : "memory")

__device__ __forceinline__ void ldsm4(uint32_t& r0, uint32_t& r1, uint32_t& r2, uint32_t& r3,
                                      uint32_t addr){
    asm volatile("ldmatrix.sync.aligned.m8n8.x4.shared.b16 {%0,%1,%2,%3}, [%4];"
                 : "=r"(r0), "=r"(r1), "=r"(r2), "=r"(r3) : "r"(addr));
}
__device__ __forceinline__ void mma_f16(float* c, const uint32_t* a, const uint32_t* b){
    asm volatile(
        "mma.sync.aligned.m16n8k16.row.col.f32.f16.f16.f32 "
        "{%0,%1,%2,%3}, {%4,%5,%6,%7}, {%8,%9}, {%0,%1,%2,%3};"
        : "+f"(c[0]), "+f"(c[1]), "+f"(c[2]), "+f"(c[3])
        : "r"(a[0]), "r"(a[1]), "r"(a[2]), "r"(a[3]), "r"(b[0]), "r"(b[1]));
}
__device__ __forceinline__ void spin_until(const int* p, int target){
    while (true){
        int v;
        asm volatile("ld.global.acquire.gpu.b32 %0, [%1];" : "=r"(v) : "l"(p));
        if (v >= target) break;
        __nanosleep(128);
    }
}
__device__ __forceinline__ void spin0(const int* p, int target){
    if (threadIdx.x == 0) spin_until(p, target);
    __syncthreads();
}
__device__ __forceinline__ void mark_done(int* p){
    __threadfence();
    atomicAdd(p, 1);
}

// =====================================================================
// Launch 1: fuseA producers + fb students + kn matvec, 512 thr
// =====================================================================
#define NPROD 33
#define FB0   97
#define NB_FB 3125
#define KN0   (FB0 + NB_FB)
#define NB_KNMV 32
#define NB_L1 (KN0 + NB_KNMV)

__global__ void __launch_bounds__(512) k_fuseAB(
    const float* __restrict__ Wg, const float* __restrict__ a_src,
    const float* __restrict__ a_dst, const float* __restrict__ exer,
    const float* __restrict__ stu, const float* __restrict__ kn,
    const int* __restrict__ eeu)
{
    __shared__ float sv[KDIM];
    __shared__ float red[KDIM];
    __shared__ float tile[64][65];
    __shared__ float s0[KDIM], s1[KDIM], s2[KDIM];
    __shared__ float sden[EN];
    int b = blockIdx.x, tid = threadIdx.x;
    int warp = tid >> 5, lane = tid & 31;

    if (b < 8) {
        int g = b >> 1, w = b & 1;
        const float* a = (w ? a_dst : a_src) + g*KDIM;
        sv[tid] = a[tid];
        __syncthreads();
        const float* Wb = Wg + (size_t)g*KDIM*KDIM;
        for (int r = warp; r < KDIM; r += 16) {
            float s = 0.f;
            for (int c = lane; c < KDIM; c += 32) s += Wb[r*KDIM + c] * sv[c];
            for (int o = 16; o; o >>= 1) s += __shfl_down_sync(0xffffffffu, s, o);
            if (lane == 0) g_wa[g][w][r] = s;
        }
        __syncthreads();
        if (tid == 0) mark_done(&g_cA);
    } else if (b < 32) {
        int t = b - 8, g = t / EN, j = t % EN;
        sv[tid] = exer[j*KDIM + tid];
        __syncthreads();
        const float* Wb = Wg + (size_t)g*KDIM*KDIM;
        float acc = 0.f;
        for (int i = 0; i < KDIM; i++) acc += sv[i] * Wb[i*KDIM + tid];
        g_he[g][j][tid] = acc;
        red[tid] = acc * a_src[g*KDIM + tid];
        __syncthreads();
        for (int o = 256; o; o >>= 1){ if (tid < o) red[tid] += red[tid+o]; __syncthreads(); }
        if (tid == 0) g_ase[g][j] = red[0];
        __syncthreads();
        red[tid] = acc * a_dst[g*KDIM + tid];
        __syncthreads();
        for (int o = 256; o; o >>= 1){ if (tid < o) red[tid] += red[tid+o]; __syncthreads(); }
        if (tid == 0){ g_ade[g][j] = red[0]; mark_done(&g_cA); }
    } else if (b < 96) {
        // coalesced 64x64 tile transpose of W2 into g_Wh (fp16); phaseC-only
        int t = b - 32;
        int row0 = (t >> 3)*64, col0 = (t & 7)*64;
        const float* W2 = Wg + 2*KDIM*KDIM;
        for (int i = tid; i < 4096; i += 512){
            int r = i >> 6, c = i & 63;
            tile[r][c] = W2[(size_t)(row0 + r)*KDIM + col0 + c];
        }
        __syncthreads();
        for (int i = tid; i < 4096; i += 512){
            int n = i >> 6, k = i & 63;
            g_Wh[(size_t)(col0 + n)*KDIM + row0 + k] = __float2half_rn(tile[k][n]);
        }
    } else if (b == 96) {
        if (tid < EN) g_den3[tid] = 0.f;
        if (tid == 511){ g_c1 = 0; g_c3 = 0; g_cbc = 0; }
        for (int i = tid; i < EN*KDIM; i += 512){ g_agg1[i] = 0.f; g_agg3[i] = 0.f; }
        __syncthreads();
        if (tid == 0) mark_done(&g_cA);
    } else if (b < KN0) {
        // fb students: fp16 convert + 3-way matvec + den3 accumulation
        spin0(&g_cA, NPROD);
        int idx = b - FB0;
        for (int i = tid; i < KDIM; i += 512){
            s0[i] = g_wa[2][0][i]; s1[i] = g_wa[2][1][i]; s2[i] = g_wa[3][0][i];
        }
        if (tid < EN) sden[tid] = 0.f;
        __syncthreads();
        if (idx == 0 && tid < EN)
            atomicAdd(&g_den3[tid], expf(lrelu(g_ase[3][tid] + g_ade[3][tid])));
        int row = idx*16 + warp;
        const float4* xr = (const float4*)(stu + (size_t)row*KDIM);
        __half2* h2 = (__half2*)(g_Ah + (size_t)row*KDIM);
        float a0 = 0.f, a1 = 0.f, a2 = 0.f;
        #pragma unroll
        for (int i = 0; i < 4; i++){
            int q = lane + 32*i;
            float4 f = xr[q];
            int c = 4*q;
            a0 += f.x*s0[c] + f.y*s0[c+1] + f.z*s0[c+2] + f.w*s0[c+3];
            a1 += f.x*s1[c] + f.y*s1[c+1] + f.z*s1[c+2] + f.w*s1[c+3];
            a2 += f.x*s2[c] + f.y*s2[c+1] + f.z*s2[c+2] + f.w*s2[c+3];
            h2[2*q]   = __floats2half2_rn(f.x, f.y);
            h2[2*q+1] = __floats2half2_rn(f.z, f.w);
        }
        for (int o = 16; o; o >>= 1){
            a0 += __shfl_down_sync(0xffffffffu, a0, o);
            a1 += __shfl_down_sync(0xffffffffu, a1, o);
            a2 += __shfl_down_sync(0xffffffffu, a2, o);
        }
        if (lane == 0){
            g_as2[row] = a0; g_ad2[row] = a1; g_as3[row] = a2;
            #pragma unroll
            for (int j = 0; j < 3; j++){
                int d = eeu[NE3 + 3*row + j];
                atomicAdd(&sden[d], expf(lrelu(a2 + g_ade[3][d])));
            }
        }
        __syncthreads();
        if (tid < EN && sden[tid] != 0.f) atomicAdd(&g_den3[tid], sden[tid]);
    } else {
        // kn 3-way matvec
        spin0(&g_cA, NPROD);
        int idx = b - KN0;
        for (int i = tid; i < KDIM; i += 512){
            s0[i] = g_wa[0][0][i]; s1[i] = g_wa[0][1][i]; s2[i] = g_wa[1][0][i];
        }
        __syncthreads();
        int row = idx*16 + warp;
        float a0 = 0.f, a1 = 0.f, a2 = 0.f;
        const float* xr = kn + (size_t)row*KDIM;
        for (int c = lane; c < KDIM; c += 32){
            float v = xr[c]; a0 += v*s0[c]; a1 += v*s1[c]; a2 += v*s2[c];
        }
        for (int o = 16; o; o >>= 1){
            a0 += __shfl_down_sync(0xffffffffu, a0, o);
            a1 += __shfl_down_sync(0xffffffffu, a1, o);
            a2 += __shfl_down_sync(0xffffffffu, a2, o);
        }
        if (lane == 0){ g_as0[row] = a0; g_ad0[row] = a1; g_as1[row] = a2; }
    }
}

// =====================================================================
// Phase C bodies
// =====================================================================
#define A_STG 10240
#define STG   20480
#define RING  (4*STG)                          // 81920
#define MMA_SMEM (RING + (EN*128 + 128 + 32)*4)

#define NB_GEMM 1564
#define NB_AGG1 8
#define NB_KN   16
#define NB_BC   12
#define NB_EXER 1
#define OFF_AGG1 (NB_GEMM)
#define OFF_KNG  (OFF_AGG1 + NB_AGG1)
#define OFF_BC   (OFF_KNG + NB_KN)
#define OFF_EXER (OFF_BC + NB_BC)
#define NB_C     (OFF_EXER + NB_EXER)

// ---- student GEMM with fused GAT2 epilogue AND fused GAT3 aggregation ----
__device__ __forceinline__ void gemm_body(
    char* dsm, int bx, int by, const int* __restrict__ esrc,
    const float* __restrict__ bg, float* __restrict__ out)
{
    float* he_s   = (float*)(dsm + RING);
    float* b_s    = he_s + EN*128;
    float* ase_s  = b_s + 128;
    float* ade3_s = ase_s + EN;
    float* iden3_s= ade3_s + EN;

    const uint32_t sb = smem_u32(dsm);
    int tid = threadIdx.x, lane = tid & 31, wid = tid >> 5;
    int mBase = by * 128, nBase = bx * 128;

    for (int i = tid; i < EN*128; i += 256)
        he_s[i] = g_he[2][i >> 7][nBase + (i & 127)];
    if (tid < 128) b_s[tid] = bg[2*KDIM + nBase + tid];
    if (tid < EN){
        ase_s[tid]  = g_ase[2][tid];
        ade3_s[tid] = g_ade[3][tid];
        iden3_s[tid]= 1.f / g_den3[tid];
    }

    const char* gA = (const char*)g_Ah;
    const char* gW = (const char*)g_Wh;

    auto load_stage = [&](int s, int chunk){
        uint32_t base = sb + s*STG;
        int kB = chunk*64;
        #pragma unroll
        for (int u = tid; u < 512; u += 256){
            int rowi = u >> 2, cc = u & 3;
            uint32_t dst = (uint32_t)(rowi*80 + cc*16);
            int gr = mBase + rowi; if (gr >= S_N) gr = S_N - 1;
            cpa16(base + dst,          gA + (size_t)gr*(KDIM*2) + kB + cc*16);
            cpa16(base + A_STG + dst,  gW + (size_t)(nBase + rowi)*(KDIM*2) + kB + cc*16);
        }
    };

    float acc[2][8][4];
    #pragma unroll
    for (int a = 0; a < 2; a++)
        #pragma unroll
        for (int b2 = 0; b2 < 8; b2++)
            #pragma unroll
            for (int c = 0; c < 4; c++) acc[a][b2][c] = 0.f;

    int wm = (wid & 3) * 32;
    int wn = (wid >> 2) * 64;
    uint32_t aOff = (uint32_t)((lane & 15)*80 + (lane >> 4)*16);
    uint32_t bOff = (uint32_t)(((lane & 7) + ((lane >> 4) << 3))*80 + (((lane >> 3) & 1) << 4));

    load_stage(0, 0); CPA_COMMIT();
    load_stage(1, 1); CPA_COMMIT();
    load_stage(2, 2); CPA_COMMIT();

    for (int c = 0; c < 16; c++){
        if (c < 14){ CPA_WAIT(2); }
        else if (c == 14){ CPA_WAIT(1); }
        else { CPA_WAIT(0); }
        __syncthreads();
        if (c < 13){ load_stage((c + 3) & 3, c + 3); CPA_COMMIT(); }

        uint32_t base = sb + (c & 3)*STG;
        uint32_t aB = base + wm*80 + aOff;
        uint32_t bB = base + A_STG + wn*80 + bOff;

        #pragma unroll
        for (int ks = 0; ks < 2; ks++){
            uint32_t ah[2][4], bh[16];
            #pragma unroll
            for (int mf = 0; mf < 2; mf++)
                ldsm4(ah[mf][0], ah[mf][1], ah[mf][2], ah[mf][3],
                      aB + mf*16*80 + ks*32);
            #pragma unroll
            for (int p = 0; p < 4; p++)
                ldsm4(bh[p*4+0], bh[p*4+1], bh[p*4+2], bh[p*4+3],
                      bB + p*16*80 + ks*32);
            #pragma unroll
            for (int mf = 0; mf < 2; mf++)
                #pragma unroll
                for (int nf = 0; nf < 8; nf++)
                    mma_f16(acc[mf][nf], ah[mf], &bh[nf*2]);
        }
    }

    // sagg overlay in ring slot 0 (last read at chunk 12; all warps past the
    // c=15 barrier, so slots 0-2 are dead). 6x128 floats = 3KB.
    float* sagg = (float*)dsm;
    for (int i = tid; i < EN*128; i += 256) sagg[i] = 0.f;
    __syncthreads();

    #pragma unroll
    for (int mf = 0; mf < 2; mf++){
        #pragma unroll
        for (int half = 0; half < 2; half++){
            int row = mBase + wm + mf*16 + (lane >> 2) + half*8;
            bool ok = row < S_N;
            int rr = ok ? row : S_N - 1;
            float adv = g_ad2[rr], asv = g_as2[rr];
            float eself = lrelu(asv + adv);
            int e0 = esrc[rr*3], e1 = esrc[rr*3 + 1], e2 = esrc[rr*3 + 2];
            float v0 = lrelu(ase_s[e0] + adv);
            float v1 = lrelu(ase_s[e1] + adv);
            float v2 = lrelu(ase_s[e2] + adv);
            float mx = fmaxf(fmaxf(eself, v0), fmaxf(v1, v2));
            float aS = expf(eself - mx), a0 = expf(v0 - mx);
            float a1 = expf(v1 - mx),  a2 = expf(v2 - mx);
            float inv = 1.f / (aS + a0 + a1 + a2);
            aS *= inv; a0 *= inv; a1 *= inv; a2 *= inv;
            // GAT3 weights (dst exercises are the SAME e0..e2 indices)
            float as3v = g_as3[rr];
            float w0 = ok ? expf(lrelu(as3v + ade3_s[e0]))*iden3_s[e0] : 0.f;
            float w1 = ok ? expf(lrelu(as3v + ade3_s[e1]))*iden3_s[e1] : 0.f;
            float w2 = ok ? expf(lrelu(as3v + ade3_s[e2]))*iden3_s[e2] : 0.f;
            #pragma unroll
            for (int nf = 0; nf < 8; nf++){
                int cl = wn + nf*8 + (lane & 3)*2;
                int col = nBase + cl;
                float2 xv = __half22float2(
                    *(const __half2*)(g_Ah + (size_t)rr*KDIM + col));
                #pragma unroll
                for (int j = 0; j < 2; j++){
                    float xval = j ? xv.y : xv.x;
                    float v = xval + b_s[cl + j]
                            + aS*acc[mf][nf][half*2 + j]
                            + a0*he_s[e0*128 + cl + j] + a1*he_s[e1*128 + cl + j]
                            + a2*he_s[e2*128 + cl + j];
                    if (ok) out[(size_t)row*KDIM + col + j] = v;
                    atomicAdd(&sagg[e0*128 + cl + j], w0*xval);
                    atomicAdd(&sagg[e1*128 + cl + j], w1*xval);
                    atomicAdd(&sagg[e2*128 + cl + j], w2*xval);
                }
            }
        }
    }
    __syncthreads();
    for (int i = tid; i < EN*128; i += 256)
        atomicAdd(&g_agg3[(i >> 7)*KDIM + nBase + (i & 127)], sagg[i]);
    __syncthreads();
    if (tid == 0) mark_done(&g_c3);
}

__device__ void agg1_body(char* dsm, int idx, const int* __restrict__ ek,
                          const float* __restrict__ kn)
{
    float* sagg = (float*)dsm;
    float* sal  = sagg + EN*KDIM;
    int*   sd   = (int*)(sal + 256);
    int*   ss   = sd + 256;
    float* sden = (float*)(ss + 256);
    int tid = threadIdx.x;
    for (int i = tid; i < EN*KDIM; i += 256) sagg[i] = 0.f;
    if (tid < EN) sden[tid] = expf(lrelu(g_ase[1][tid] + g_ade[1][tid]));
    __syncthreads();
    for (int t = tid; t < 2048; t += 256){
        int k = ek[t] - EN, d = ek[2048 + t];
        atomicAdd(&sden[d], expf(lrelu(g_as1[k] + g_ade[1][d])));
    }
    __syncthreads();
    int t = idx*256 + tid;
    {
        int k = ek[t] - EN, d = ek[2048 + t];
        sal[tid] = expf(lrelu(g_as1[k] + g_ade[1][d])) / sden[d];
        sd[tid] = d; ss[tid] = k;
    }
    if (idx == 0 && tid < EN) g_den1[tid] = sden[tid];
    __syncthreads();
    for (int el = 0; el < 256; el++){
        int d = sd[el]; float al = sal[el];
        const float* kr = kn + (size_t)ss[el]*KDIM;
        sagg[d*KDIM + tid]       += al*kr[tid];
        sagg[d*KDIM + 256 + tid] += al*kr[256 + tid];
    }
    __syncthreads();
    for (int i = tid; i < EN*KDIM; i += 256) atomicAdd(&g_agg1[i], sagg[i]);
    __syncthreads();
    if (tid == 0) mark_done(&g_c1);
}

__device__ void gemm_gat_body(char* dsm, int idx,
                              const float* __restrict__ A, const float* __restrict__ W,
                              const float* __restrict__ b, const int* __restrict__ esrc,
                              float* __restrict__ out)
{
    float (*As)[128] = (float(*)[128])dsm;
    float (*Bs)[128] = (float(*)[128])(dsm + 4096);
    float* he_s  = (float*)(dsm + 8192);
    float* b_s   = he_s + EN*128;
    float* ase_s = b_s + 128;
    int tid = threadIdx.x;
    int tx = tid & 15, ty = tid >> 4;
    int colBase = (idx & 3)*128, rowBase = (idx >> 2)*128;

    if (tid < 128) b_s[tid] = b[colBase + tid];
    if (tid >= 128 && tid < 128 + EN) ase_s[tid - 128] = g_ase[0][tid - 128];
    for (int i = tid; i < EN*128; i += 256)
        he_s[i] = g_he[0][i >> 7][colBase + (i & 127)];

    int aRow = tid >> 1, aCol = (tid & 1)*4;
    int bRow = tid >> 5, bCol = (tid & 31)*4;
    const float* Aptr = A + (size_t)(rowBase + aRow)*KDIM + aCol;
    const float* Wptr = W + (size_t)bRow*KDIM + colBase + bCol;

    float acc[8][8];
    #pragma unroll
    for (int i = 0; i < 8; i++)
        #pragma unroll
        for (int j = 0; j < 8; j++) acc[i][j] = 0.f;

    for (int k0 = 0; k0 < KDIM; k0 += 8){
        float4 av = *(const float4*)(Aptr + k0);
        float4 wv = *(const float4*)(Wptr + (size_t)k0*KDIM);
        __syncthreads();
        As[aCol+0][aRow] = av.x; As[aCol+1][aRow] = av.y;
        As[aCol+2][aRow] = av.z; As[aCol+3][aRow] = av.w;
        *(float4*)&Bs[bRow][bCol] = wv;
        __syncthreads();
        #pragma unroll
        for (int kk = 0; kk < 8; kk++){
            float4 a0 = *(const float4*)&As[kk][ty*8];
            float4 a1 = *(const float4*)&As[kk][ty*8 + 4];
            float4 b0 = *(const float4*)&Bs[kk][tx*8];
            float4 b1 = *(const float4*)&Bs[kk][tx*8 + 4];
            float ar[8] = {a0.x,a0.y,a0.z,a0.w,a1.x,a1.y,a1.z,a1.w};
            float br[8] = {b0.x,b0.y,b0.z,b0.w,b1.x,b1.y,b1.z,b1.w};
            #pragma unroll
            for (int i = 0; i < 8; i++)
                #pragma unroll
                for (int j = 0; j < 8; j++)
                    acc[i][j] += ar[i]*br[j];
        }
    }

    #pragma unroll
    for (int i = 0; i < 8; i++){
        int row = rowBase + ty*8 + i;
        float asv = g_as0[row], adv = g_ad0[row];
        float eself = lrelu(asv + adv);
        float mx = eself;
        int srcs[4]; float ev[4];
        #pragma unroll
        for (int j = 0; j < 4; j++){
            int s = esrc[row*4 + j];
            srcs[j] = s;
            float e = lrelu(ase_s[s] + adv);
            ev[j] = e; mx = fmaxf(mx, e);
        }
        float aself = expf(eself - mx);
        float se = aself;
        float al[4];
        #pragma unroll
        for (int j = 0; j < 4; j++){ al[j] = expf(ev[j] - mx); se += al[j]; }
        float inv = 1.f / se;
        aself *= inv;
        #pragma unroll
        for (int j = 0; j < 4; j++) al[j] *= inv;

        const float* xr = A + (size_t)row*KDIM + colBase;
        float* orow = out + (size_t)row*KDIM + colBase;
        #pragma unroll
        for (int jj = 0; jj < 8; jj++){
            int c = tx*8 + jj;
            float v = xr[c] + b_s[c] + aself*acc[i][jj];
            #pragma unroll
            for (int j = 0; j < 4; j++) v += al[j]*he_s[srcs[j]*128 + c];
            orow[c] = v;
        }
    }
}

__device__ void bc_body(char* dsm, int r, const float* __restrict__ Wg,
                        const float* __restrict__ bg, const float* __restrict__ exer)
{
    if (threadIdx.x == 0){ spin_until(&g_c1, NB_AGG1); spin_until(&g_c3, NB_GEMM); }
    __syncthreads();
    float* srow = (float*)dsm;
    int tid = threadIdx.x;
    int isB = (r < EN) ? 1 : 0;
    int e = isB ? r : r - EN;
    int g = isB ? 1 : 3;
    float den = isB ? g_den1[e] : g_den3[e];
    float aself = expf(lrelu(g_ase[g][e] + g_ade[g][e])) / den;
    const float* agg = isB ? g_agg1 : g_agg3;
    srow[tid]       = agg[e*KDIM + tid]       + aself * exer[e*KDIM + tid];
    srow[tid + 256] = agg[e*KDIM + tid + 256] + aself * exer[e*KDIM + tid + 256];
    __syncthreads();
    const float* Wb = Wg + (size_t)g*KDIM*KDIM;
    float acc0 = bg[g*KDIM + tid], acc1 = bg[g*KDIM + tid + 256];
    for (int i = 0; i < KDIM; i++){
        float s = srow[i];
        acc0 += s * Wb[i*KDIM + tid];
        acc1 += s * Wb[i*KDIM + tid + 256];
    }
    float* dst = isB ? g_B : g_C;
    dst[e*KDIM + tid] = acc0;
    dst[e*KDIM + tid + 256] = acc1;
    __syncthreads();
    if (threadIdx.x == 0) mark_done(&g_cbc);
}

__device__ void exer_body(char* dsm, const float* __restrict__ exer,
                          const float* __restrict__ aw, const float* __restrict__ ab,
                          float* __restrict__ outE)
{
    spin0(&g_cbc, NB_BC);
    float* red = (float*)dsm;
    int tid = threadIdx.x;
    for (int e = 0; e < EN; e++){
        float xv0 = exer[e*KDIM + tid],       xv1 = exer[e*KDIM + tid + 256];
        float bv0 = g_B[e*KDIM + tid],        bv1 = g_B[e*KDIM + tid + 256];
        float cv0 = g_C[e*KDIM + tid],        cv1 = g_C[e*KDIM + tid + 256];
        red[tid] = xv0*aw[1024 + tid]       + bv0*aw[1024 + KDIM + tid]
                 + xv1*aw[1024 + tid + 256] + bv1*aw[1024 + KDIM + tid + 256];
        __syncthreads();
        for (int o = 128; o; o >>= 1){ if (tid < o) red[tid] += red[tid+o]; __syncthreads(); }
        float s1 = red[0] + ab[1];
        __syncthreads();
        red[tid] = xv0*aw[2048 + tid]       + cv0*aw[2048 + KDIM + tid]
                 + xv1*aw[2048 + tid + 256] + cv1*aw[2048 + KDIM + tid + 256];
        __syncthreads();
        for (int o = 128; o; o >>= 1){ if (tid < o) red[tid] += red[tid+o]; __syncthreads(); }
        float s2 = red[0] + ab[2];
        __syncthreads();
        float mx = fmaxf(s1, s2);
        float e1 = expf(s1 - mx), e2 = expf(s2 - mx);
        float inv = 1.f / (e1 + e2);
        float w1 = e1*inv, w2 = e2*inv;
        outE[e*KDIM + tid]       = xv0 + w1*bv0 + w2*cv0;
        outE[e*KDIM + tid + 256] = xv1 + w1*bv1 + w2*cv1;
    }
    // reset launch-1 producer counter for the next graph replay
    __syncthreads();
    if (tid == 0){ __threadfence(); g_cA = 0; }
}

// Phase C: GEMM(+agg3 fused) + agg1 + kn-GEMM + bc + exer, one launch
__global__ void __launch_bounds__(256, 2) k_phaseC(
    const int* __restrict__ eue, const int* __restrict__ eek,
    const int* __restrict__ eke, const float* __restrict__ kn,
    const float* __restrict__ Wg, const float* __restrict__ bg,
    const float* __restrict__ exer, const float* __restrict__ aw,
    const float* __restrict__ ab,
    float* __restrict__ out_st, float* __restrict__ out_kn,
    float* __restrict__ out_ex)
{
    extern __shared__ __align__(16) char dsm[];
    int b = blockIdx.x;
    if (b < NB_GEMM){
        gemm_body(dsm, b & 3, b >> 2, eue, bg, out_st);
    } else if (b < OFF_KNG){
        agg1_body(dsm, b - OFF_AGG1, eek, kn);
    } else if (b < OFF_BC){
        gemm_gat_body(dsm, b - OFF_KNG, kn, Wg, bg, eke, out_kn);
    } else if (b < OFF_EXER){
        bc_body(dsm, b - OFF_BC, Wg, bg, exer);
    } else {
        exer_body(dsm, exer, aw, ab, out_ex);
    }
}

// ---------------- launcher ----------------
extern "C" void kernel_launch(void* const* d_in, const int* in_sizes, int n_in,
                              void* d_out, int out_size){
    const float* kn   = (const float*)d_in[0];
    const float* exer = (const float*)d_in[1];
    const float* stu  = (const float*)d_in[2];
    const float* Wg   = (const float*)d_in[3];
    const float* a_s  = (const float*)d_in[4];
    const float* a_d  = (const float*)d_in[5];
    const float* bg   = (const float*)d_in[6];
    const float* aw   = (const float*)d_in[7];
    const float* ab   = (const float*)d_in[8];
    const int* eke    = (const int*)d_in[9];
    const int* eek    = (const int*)d_in[10];
    const int* eue    = (const int*)d_in[11];
    const int* eeu    = (const int*)d_in[12];
    (void)in_sizes; (void)n_in; (void)out_size;

    float* out    = (float*)d_out;
    float* out_kn = out;
    float* out_ex = out + KDIM*KDIM;
    float* out_st = out + KDIM*KDIM + EN*KDIM;

    static int s_attr_done = 0;
    if (!s_attr_done){
        cudaFuncSetAttribute(k_phaseC, cudaFuncAttributeMaxDynamicSharedMemorySize,
                             MMA_SMEM);
        s_attr_done = 1;
    }

    k_fuseAB<<<NB_L1, 512>>>(Wg, a_s, a_d, exer, stu, kn, eeu);
    k_phaseC<<<NB_C, 256, MMA_SMEM>>>(
        eue, eek, eke, kn, Wg, bg, exer, aw, ab, out_st, out_kn, out_ex);
}

// round 16
// speedup vs baseline: 1.4436x; 1.4436x over previous
#include <cuda_runtime.h>
#include <cuda_fp16.h>
#include <cstdint>

#define KDIM 512
#define S_N 50000
#define EN 6
#define NEG 0.2f
#define NE3 150000

// ---------------- scratch (static __device__, no allocation) ----------------
__device__ float g_wa[4][2][KDIM];      // W_g @ a_src / a_dst
__device__ float g_he[4][EN][KDIM];     // exer_emb @ W_g
__device__ float g_ase[4][EN];          // h_e . a_src
__device__ float g_ade[4][EN];          // h_e . a_dst
__device__ float g_as2[S_N], g_ad2[S_N], g_as3[S_N];
__device__ float g_as0[KDIM], g_ad0[KDIM], g_as1[KDIM];
__device__ float g_den1[EN], g_den3[EN];
__device__ float g_agg1[EN*KDIM];
__device__ float g_agg3p[4][EN*KDIM];   // un-normalized GAT3 staging (4-way)
__device__ float g_B[EN*KDIM], g_C[EN*KDIM];
// counters: g_cA zeroed by phaseC's exer (prev replay) / static init;
// g_c1/g_cbc zeroed by launch-1's init block (ordered before phaseC).
__device__ int g_cA, g_c1, g_cbc;

// fp16 operands for the tensor-core student GEMM
__device__ __half g_Ah[(size_t)S_N*KDIM];
__device__ __half g_Wh[KDIM*KDIM];   // W2^T: [n][k]

__device__ __forceinline__ float lrelu(float x){ return x > 0.f ? x : NEG*x; }

// ---------------- PTX helpers (all legal on plain compute_103) ----------------
__device__ __forceinline__ uint32_t smem_u32(const void* p){
    uint32_t a;
    asm("{ .reg .u64 t; cvta.to.shared.u64 t, %1; cvt.u32.u64 %0, t; }" : "=r"(a) : "l"(p));
    return a;
}
__device__ __forceinline__ void cpa16(uint32_t s, const void* g){
    asm volatile("cp.async.cg.shared.global [%0], [%1], 16;" :: "r"(s), "l"(g));
}
#define CPA_COMMIT() asm volatile("cp.async.commit_group;" ::: "memory")
#define CPA_WAIT(n)  asm volatile("cp.async.wait_group %0;" :: "n"(n) : "memory")

__device__ __forceinline__ void ldsm4(uint32_t& r0, uint32_t& r1, uint32_t& r2, uint32_t& r3,
                                      uint32_t addr){
    asm volatile("ldmatrix.sync.aligned.m8n8.x4.shared.b16 {%0,%1,%2,%3}, [%4];"
                 : "=r"(r0), "=r"(r1), "=r"(r2), "=r"(r3) : "r"(addr));
}
__device__ __forceinline__ void mma_f16(float* c, const uint32_t* a, const uint32_t* b){
    asm volatile(
        "mma.sync.aligned.m16n8k16.row.col.f32.f16.f16.f32 "
        "{%0,%1,%2,%3}, {%4,%5,%6,%7}, {%8,%9}, {%0,%1,%2,%3};"
        : "+f"(c[0]), "+f"(c[1]), "+f"(c[2]), "+f"(c[3])
        : "r"(a[0]), "r"(a[1]), "r"(a[2]), "r"(a[3]), "r"(b[0]), "r"(b[1]));
}
__device__ __forceinline__ void spin_until(const int* p, int target){
    while (true){
        int v;
        asm volatile("ld.global.acquire.gpu.b32 %0, [%1];" : "=r"(v) : "l"(p));
        if (v >= target) break;
        __nanosleep(128);
    }
}
__device__ __forceinline__ void spin0(const int* p, int target){
    if (threadIdx.x == 0) spin_until(p, target);
    __syncthreads();
}
__device__ __forceinline__ void mark_done(int* p){
    __threadfence();
    atomicAdd(p, 1);
}

// =====================================================================
// Launch 1: fuseA producers + fb students (+un-normalized agg3) + kn matvec
// =====================================================================
#define NPROD 33
#define FB0   97
#define NB_FB 3125
#define KN0   (FB0 + NB_FB)
#define NB_KNMV 32
#define NB_L1 (KN0 + NB_KNMV)

__global__ void __launch_bounds__(512) k_fuseAB(
    const float* __restrict__ Wg, const float* __restrict__ a_src,
    const float* __restrict__ a_dst, const float* __restrict__ exer,
    const float* __restrict__ stu, const float* __restrict__ kn,
    const int* __restrict__ eeu)
{
    __shared__ float sv[KDIM];
    __shared__ float red[KDIM];
    __shared__ float tile[64][65];
    __shared__ float s0[KDIM], s1[KDIM], s2[KDIM];
    __shared__ float sagg[EN*KDIM];     // 12KB un-normalized agg3 accumulator
    __shared__ float sden[EN];
    int b = blockIdx.x, tid = threadIdx.x;
    int warp = tid >> 5, lane = tid & 31;

    if (b < 8) {
        int g = b >> 1, w = b & 1;
        const float* a = (w ? a_dst : a_src) + g*KDIM;
        sv[tid] = a[tid];
        __syncthreads();
        const float* Wb = Wg + (size_t)g*KDIM*KDIM;
        for (int r = warp; r < KDIM; r += 16) {
            float s = 0.f;
            for (int c = lane; c < KDIM; c += 32) s += Wb[r*KDIM + c] * sv[c];
            for (int o = 16; o; o >>= 1) s += __shfl_down_sync(0xffffffffu, s, o);
            if (lane == 0) g_wa[g][w][r] = s;
        }
        __syncthreads();
        if (tid == 0) mark_done(&g_cA);
    } else if (b < 32) {
        int t = b - 8, g = t / EN, j = t % EN;
        sv[tid] = exer[j*KDIM + tid];
        __syncthreads();
        const float* Wb = Wg + (size_t)g*KDIM*KDIM;
        float acc = 0.f;
        for (int i = 0; i < KDIM; i++) acc += sv[i] * Wb[i*KDIM + tid];
        g_he[g][j][tid] = acc;
        red[tid] = acc * a_src[g*KDIM + tid];
        __syncthreads();
        for (int o = 256; o; o >>= 1){ if (tid < o) red[tid] += red[tid+o]; __syncthreads(); }
        if (tid == 0) g_ase[g][j] = red[0];
        __syncthreads();
        red[tid] = acc * a_dst[g*KDIM + tid];
        __syncthreads();
        for (int o = 256; o; o >>= 1){ if (tid < o) red[tid] += red[tid+o]; __syncthreads(); }
        if (tid == 0){ g_ade[g][j] = red[0]; mark_done(&g_cA); }
    } else if (b < 96) {
        // coalesced 64x64 tile transpose of W2 into g_Wh (fp16); phaseC-only
        int t = b - 32;
        int row0 = (t >> 3)*64, col0 = (t & 7)*64;
        const float* W2 = Wg + 2*KDIM*KDIM;
        for (int i = tid; i < 4096; i += 512){
            int r = i >> 6, c = i & 63;
            tile[r][c] = W2[(size_t)(row0 + r)*KDIM + col0 + c];
        }
        __syncthreads();
        for (int i = tid; i < 4096; i += 512){
            int n = i >> 6, k = i & 63;
            g_Wh[(size_t)(col0 + n)*KDIM + row0 + k] = __float2half_rn(tile[k][n]);
        }
    } else if (b == 96) {
        if (tid < EN) g_den3[tid] = 0.f;
        if (tid == 511){ g_c1 = 0; g_cbc = 0; }
        for (int i = tid; i < EN*KDIM; i += 512){
            g_agg1[i] = 0.f;
            g_agg3p[0][i] = 0.f; g_agg3p[1][i] = 0.f;
            g_agg3p[2][i] = 0.f; g_agg3p[3][i] = 0.f;
        }
        __syncthreads();
        if (tid == 0) mark_done(&g_cA);
    } else if (b < KN0) {
        // fb students: fp16 convert + 3-way matvec + den3 + UN-NORMALIZED agg3
        spin0(&g_cA, NPROD);
        int idx = b - FB0;
        for (int i = tid; i < KDIM; i += 512){
            s0[i] = g_wa[2][0][i]; s1[i] = g_wa[2][1][i]; s2[i] = g_wa[3][0][i];
        }
        for (int i = tid; i < EN*KDIM; i += 512) sagg[i] = 0.f;
        if (tid < EN) sden[tid] = 0.f;
        __syncthreads();
        if (idx == 0 && tid < EN)
            atomicAdd(&g_den3[tid], expf(lrelu(g_ase[3][tid] + g_ade[3][tid])));
        int row = idx*16 + warp;
        const float4* xr = (const float4*)(stu + (size_t)row*KDIM);
        __half2* h2 = (__half2*)(g_Ah + (size_t)row*KDIM);
        float a0 = 0.f, a1 = 0.f, a2 = 0.f;
        #pragma unroll
        for (int i = 0; i < 4; i++){
            int q = lane + 32*i;
            float4 f = xr[q];
            int c = 4*q;
            a0 += f.x*s0[c] + f.y*s0[c+1] + f.z*s0[c+2] + f.w*s0[c+3];
            a1 += f.x*s1[c] + f.y*s1[c+1] + f.z*s1[c+2] + f.w*s1[c+3];
            a2 += f.x*s2[c] + f.y*s2[c+1] + f.z*s2[c+2] + f.w*s2[c+3];
            h2[2*q]   = __floats2half2_rn(f.x, f.y);
            h2[2*q+1] = __floats2half2_rn(f.z, f.w);
        }
        // butterfly so ALL lanes hold the reduced values
        #pragma unroll
        for (int o = 16; o; o >>= 1){
            a0 += __shfl_xor_sync(0xffffffffu, a0, o);
            a1 += __shfl_xor_sync(0xffffffffu, a1, o);
            a2 += __shfl_xor_sync(0xffffffffu, a2, o);
        }
        if (lane == 0){ g_as2[row] = a0; g_ad2[row] = a1; g_as3[row] = a2; }
        // GAT3 edges for this student
        int d0 = eeu[NE3 + 3*row], d1 = eeu[NE3 + 3*row + 1], d2 = eeu[NE3 + 3*row + 2];
        float w0 = expf(lrelu(a2 + g_ade[3][d0]));
        float w1 = expf(lrelu(a2 + g_ade[3][d1]));
        float w2 = expf(lrelu(a2 + g_ade[3][d2]));
        if (lane == 0){
            atomicAdd(&sden[d0], w0); atomicAdd(&sden[d1], w1); atomicAdd(&sden[d2], w2);
        }
        // accumulate w*x (re-read x as fp16 from L2-hot g_Ah)
        const __half2* hrow = (const __half2*)(g_Ah + (size_t)row*KDIM);
        #pragma unroll
        for (int i = 0; i < 4; i++){
            int q = lane + 32*i;
            float2 xa = __half22float2(hrow[2*q]);
            float2 xb = __half22float2(hrow[2*q + 1]);
            int c = 4*q;
            atomicAdd(&sagg[d0*KDIM + c],     w0*xa.x);
            atomicAdd(&sagg[d0*KDIM + c + 1], w0*xa.y);
            atomicAdd(&sagg[d0*KDIM + c + 2], w0*xb.x);
            atomicAdd(&sagg[d0*KDIM + c + 3], w0*xb.y);
            atomicAdd(&sagg[d1*KDIM + c],     w1*xa.x);
            atomicAdd(&sagg[d1*KDIM + c + 1], w1*xa.y);
            atomicAdd(&sagg[d1*KDIM + c + 2], w1*xb.x);
            atomicAdd(&sagg[d1*KDIM + c + 3], w1*xb.y);
            atomicAdd(&sagg[d2*KDIM + c],     w2*xa.x);
            atomicAdd(&sagg[d2*KDIM + c + 1], w2*xa.y);
            atomicAdd(&sagg[d2*KDIM + c + 2], w2*xb.x);
            atomicAdd(&sagg[d2*KDIM + c + 3], w2*xb.y);
        }
        __syncthreads();
        float* dstp = g_agg3p[idx & 3];
        for (int i = tid; i < EN*KDIM; i += 512) atomicAdd(&dstp[i], sagg[i]);
        if (tid < EN && sden[tid] != 0.f) atomicAdd(&g_den3[tid], sden[tid]);
    } else {
        // kn 3-way matvec
        spin0(&g_cA, NPROD);
        int idx = b - KN0;
        for (int i = tid; i < KDIM; i += 512){
            s0[i] = g_wa[0][0][i]; s1[i] = g_wa[0][1][i]; s2[i] = g_wa[1][0][i];
        }
        __syncthreads();
        int row = idx*16 + warp;
        float a0 = 0.f, a1 = 0.f, a2 = 0.f;
        const float* xr = kn + (size_t)row*KDIM;
        for (int c = lane; c < KDIM; c += 32){
            float v = xr[c]; a0 += v*s0[c]; a1 += v*s1[c]; a2 += v*s2[c];
        }
        for (int o = 16; o; o >>= 1){
            a0 += __shfl_down_sync(0xffffffffu, a0, o);
            a1 += __shfl_down_sync(0xffffffffu, a1, o);
            a2 += __shfl_down_sync(0xffffffffu, a2, o);
        }
        if (lane == 0){ g_as0[row] = a0; g_ad0[row] = a1; g_as1[row] = a2; }
    }
}

// =====================================================================
// Phase C bodies
// =====================================================================
#define A_STG 10240
#define STG   20480
#define RING  (4*STG)                          // 81920
#define MMA_SMEM (RING + (EN*128 + 128 + 8)*4)

#define NB_GEMM 1564
#define NB_AGG1 8
#define NB_KN   16
#define NB_BC   12
#define NB_EXER 1
#define OFF_AGG1 (NB_GEMM)
#define OFF_KNG  (OFF_AGG1 + NB_AGG1)
#define OFF_BC   (OFF_KNG + NB_KN)
#define OFF_EXER (OFF_BC + NB_BC)
#define NB_C     (OFF_EXER + NB_EXER)

// ---- student GEMM with fused GAT2 epilogue (clean R11 form) ----
__device__ __forceinline__ void gemm_body(
    char* dsm, int bx, int by, const int* __restrict__ esrc,
    const float* __restrict__ bg, float* __restrict__ out)
{
    float* he_s  = (float*)(dsm + RING);
    float* b_s   = he_s + EN*128;
    float* ase_s = b_s + 128;

    const uint32_t sb = smem_u32(dsm);
    int tid = threadIdx.x, lane = tid & 31, wid = tid >> 5;
    int mBase = by * 128, nBase = bx * 128;

    for (int i = tid; i < EN*128; i += 256)
        he_s[i] = g_he[2][i >> 7][nBase + (i & 127)];
    if (tid < 128) b_s[tid] = bg[2*KDIM + nBase + tid];
    if (tid < EN) ase_s[tid] = g_ase[2][tid];

    const char* gA = (const char*)g_Ah;
    const char* gW = (const char*)g_Wh;

    auto load_stage = [&](int s, int chunk){
        uint32_t base = sb + s*STG;
        int kB = chunk*64;
        #pragma unroll
        for (int u = tid; u < 512; u += 256){
            int rowi = u >> 2, cc = u & 3;
            uint32_t dst = (uint32_t)(rowi*80 + cc*16);
            int gr = mBase + rowi; if (gr >= S_N) gr = S_N - 1;
            cpa16(base + dst,          gA + (size_t)gr*(KDIM*2) + kB + cc*16);
            cpa16(base + A_STG + dst,  gW + (size_t)(nBase + rowi)*(KDIM*2) + kB + cc*16);
        }
    };

    float acc[2][8][4];
    #pragma unroll
    for (int a = 0; a < 2; a++)
        #pragma unroll
        for (int b2 = 0; b2 < 8; b2++)
            #pragma unroll
            for (int c = 0; c < 4; c++) acc[a][b2][c] = 0.f;

    int wm = (wid & 3) * 32;
    int wn = (wid >> 2) * 64;
    uint32_t aOff = (uint32_t)((lane & 15)*80 + (lane >> 4)*16);
    uint32_t bOff = (uint32_t)(((lane & 7) + ((lane >> 4) << 3))*80 + (((lane >> 3) & 1) << 4));

    load_stage(0, 0); CPA_COMMIT();
    load_stage(1, 1); CPA_COMMIT();
    load_stage(2, 2); CPA_COMMIT();

    for (int c = 0; c < 16; c++){
        if (c < 14){ CPA_WAIT(2); }
        else if (c == 14){ CPA_WAIT(1); }
        else { CPA_WAIT(0); }
        __syncthreads();
        if (c < 13){ load_stage((c + 3) & 3, c + 3); CPA_COMMIT(); }

        uint32_t base = sb + (c & 3)*STG;
        uint32_t aB = base + wm*80 + aOff;
        uint32_t bB = base + A_STG + wn*80 + bOff;

        #pragma unroll
        for (int ks = 0; ks < 2; ks++){
            uint32_t ah[2][4], bh[16];
            #pragma unroll
            for (int mf = 0; mf < 2; mf++)
                ldsm4(ah[mf][0], ah[mf][1], ah[mf][2], ah[mf][3],
                      aB + mf*16*80 + ks*32);
            #pragma unroll
            for (int p = 0; p < 4; p++)
                ldsm4(bh[p*4+0], bh[p*4+1], bh[p*4+2], bh[p*4+3],
                      bB + p*16*80 + ks*32);
            #pragma unroll
            for (int mf = 0; mf < 2; mf++)
                #pragma unroll
                for (int nf = 0; nf < 8; nf++)
                    mma_f16(acc[mf][nf], ah[mf], &bh[nf*2]);
        }
    }

    #pragma unroll
    for (int mf = 0; mf < 2; mf++){
        #pragma unroll
        for (int half = 0; half < 2; half++){
            int row = mBase + wm + mf*16 + (lane >> 2) + half*8;
            bool ok = row < S_N;
            int rr = ok ? row : S_N - 1;
            float adv = g_ad2[rr], asv = g_as2[rr];
            float eself = lrelu(asv + adv);
            int e0 = esrc[rr*3], e1 = esrc[rr*3 + 1], e2 = esrc[rr*3 + 2];
            float v0 = lrelu(ase_s[e0] + adv);
            float v1 = lrelu(ase_s[e1] + adv);
            float v2 = lrelu(ase_s[e2] + adv);
            float mx = fmaxf(fmaxf(eself, v0), fmaxf(v1, v2));
            float aS = expf(eself - mx), a0 = expf(v0 - mx);
            float a1 = expf(v1 - mx),  a2 = expf(v2 - mx);
            float inv = 1.f / (aS + a0 + a1 + a2);
            aS *= inv; a0 *= inv; a1 *= inv; a2 *= inv;
            #pragma unroll
            for (int nf = 0; nf < 8; nf++){
                int cl = wn + nf*8 + (lane & 3)*2;
                int col = nBase + cl;
                float2 xv = __half22float2(
                    *(const __half2*)(g_Ah + (size_t)rr*KDIM + col));
                #pragma unroll
                for (int j = 0; j < 2; j++){
                    float v = (j ? xv.y : xv.x) + b_s[cl + j]
                            + aS*acc[mf][nf][half*2 + j]
                            + a0*he_s[e0*128 + cl + j] + a1*he_s[e1*128 + cl + j]
                            + a2*he_s[e2*128 + cl + j];
                    if (ok) out[(size_t)row*KDIM + col + j] = v;
                }
            }
        }
    }
}

__device__ void agg1_body(char* dsm, int idx, const int* __restrict__ ek,
                          const float* __restrict__ kn)
{
    float* sagg = (float*)dsm;
    float* sal  = sagg + EN*KDIM;
    int*   sd   = (int*)(sal + 256);
    int*   ss   = sd + 256;
    float* sden = (float*)(ss + 256);
    int tid = threadIdx.x;
    for (int i = tid; i < EN*KDIM; i += 256) sagg[i] = 0.f;
    if (tid < EN) sden[tid] = expf(lrelu(g_ase[1][tid] + g_ade[1][tid]));
    __syncthreads();
    for (int t = tid; t < 2048; t += 256){
        int k = ek[t] - EN, d = ek[2048 + t];
        atomicAdd(&sden[d], expf(lrelu(g_as1[k] + g_ade[1][d])));
    }
    __syncthreads();
    int t = idx*256 + tid;
    {
        int k = ek[t] - EN, d = ek[2048 + t];
        sal[tid] = expf(lrelu(g_as1[k] + g_ade[1][d])) / sden[d];
        sd[tid] = d; ss[tid] = k;
    }
    if (idx == 0 && tid < EN) g_den1[tid] = sden[tid];
    __syncthreads();
    for (int el = 0; el < 256; el++){
        int d = sd[el]; float al = sal[el];
        const float* kr = kn + (size_t)ss[el]*KDIM;
        sagg[d*KDIM + tid]       += al*kr[tid];
        sagg[d*KDIM + 256 + tid] += al*kr[256 + tid];
    }
    __syncthreads();
    for (int i = tid; i < EN*KDIM; i += 256) atomicAdd(&g_agg1[i], sagg[i]);
    __syncthreads();
    if (tid == 0) mark_done(&g_c1);
}

__device__ void gemm_gat_body(char* dsm, int idx,
                              const float* __restrict__ A, const float* __restrict__ W,
                              const float* __restrict__ b, const int* __restrict__ esrc,
                              float* __restrict__ out)
{
    float (*As)[128] = (float(*)[128])dsm;
    float (*Bs)[128] = (float(*)[128])(dsm + 4096);
    float* he_s  = (float*)(dsm + 8192);
    float* b_s   = he_s + EN*128;
    float* ase_s = b_s + 128;
    int tid = threadIdx.x;
    int tx = tid & 15, ty = tid >> 4;
    int colBase = (idx & 3)*128, rowBase = (idx >> 2)*128;

    if (tid < 128) b_s[tid] = b[colBase + tid];
    if (tid >= 128 && tid < 128 + EN) ase_s[tid - 128] = g_ase[0][tid - 128];
    for (int i = tid; i < EN*128; i += 256)
        he_s[i] = g_he[0][i >> 7][colBase + (i & 127)];

    int aRow = tid >> 1, aCol = (tid & 1)*4;
    int bRow = tid >> 5, bCol = (tid & 31)*4;
    const float* Aptr = A + (size_t)(rowBase + aRow)*KDIM + aCol;
    const float* Wptr = W + (size_t)bRow*KDIM + colBase + bCol;

    float acc[8][8];
    #pragma unroll
    for (int i = 0; i < 8; i++)
        #pragma unroll
        for (int j = 0; j < 8; j++) acc[i][j] = 0.f;

    for (int k0 = 0; k0 < KDIM; k0 += 8){
        float4 av = *(const float4*)(Aptr + k0);
        float4 wv = *(const float4*)(Wptr + (size_t)k0*KDIM);
        __syncthreads();
        As[aCol+0][aRow] = av.x; As[aCol+1][aRow] = av.y;
        As[aCol+2][aRow] = av.z; As[aCol+3][aRow] = av.w;
        *(float4*)&Bs[bRow][bCol] = wv;
        __syncthreads();
        #pragma unroll
        for (int kk = 0; kk < 8; kk++){
            float4 a0 = *(const float4*)&As[kk][ty*8];
            float4 a1 = *(const float4*)&As[kk][ty*8 + 4];
            float4 b0 = *(const float4*)&Bs[kk][tx*8];
            float4 b1 = *(const float4*)&Bs[kk][tx*8 + 4];
            float ar[8] = {a0.x,a0.y,a0.z,a0.w,a1.x,a1.y,a1.z,a1.w};
            float br[8] = {b0.x,b0.y,b0.z,b0.w,b1.x,b1.y,b1.z,b1.w};
            #pragma unroll
            for (int i = 0; i < 8; i++)
                #pragma unroll
                for (int j = 0; j < 8; j++)
                    acc[i][j] += ar[i]*br[j];
        }
    }

    #pragma unroll
    for (int i = 0; i < 8; i++){
        int row = rowBase + ty*8 + i;
        float asv = g_as0[row], adv = g_ad0[row];
        float eself = lrelu(asv + adv);
        float mx = eself;
        int srcs[4]; float ev[4];
        #pragma unroll
        for (int j = 0; j < 4; j++){
            int s = esrc[row*4 + j];
            srcs[j] = s;
            float e = lrelu(ase_s[s] + adv);
            ev[j] = e; mx = fmaxf(mx, e);
        }
        float aself = expf(eself - mx);
        float se = aself;
        float al[4];
        #pragma unroll
        for (int j = 0; j < 4; j++){ al[j] = expf(ev[j] - mx); se += al[j]; }
        float inv = 1.f / se;
        aself *= inv;
        #pragma unroll
        for (int j = 0; j < 4; j++) al[j] *= inv;

        const float* xr = A + (size_t)row*KDIM + colBase;
        float* orow = out + (size_t)row*KDIM + colBase;
        #pragma unroll
        for (int jj = 0; jj < 8; jj++){
            int c = tx*8 + jj;
            float v = xr[c] + b_s[c] + aself*acc[i][jj];
            #pragma unroll
            for (int j = 0; j < 4; j++) v += al[j]*he_s[srcs[j]*128 + c];
            orow[c] = v;
        }
    }
}

__device__ void bc_body(char* dsm, int r, const float* __restrict__ Wg,
                        const float* __restrict__ bg, const float* __restrict__ exer)
{
    // agg3 complete at launch boundary (fuseAB); only agg1 needs a spin
    if (threadIdx.x == 0) spin_until(&g_c1, NB_AGG1);
    __syncthreads();
    float* srow = (float*)dsm;
    int tid = threadIdx.x;
    int isB = (r < EN) ? 1 : 0;
    int e = isB ? r : r - EN;
    int g = isB ? 1 : 3;
    float den = isB ? g_den1[e] : g_den3[e];
    float iden = 1.f / den;
    float aself = expf(lrelu(g_ase[g][e] + g_ade[g][e])) * iden;
    if (isB){
        srow[tid]       = g_agg1[e*KDIM + tid]       + aself * exer[e*KDIM + tid];
        srow[tid + 256] = g_agg1[e*KDIM + tid + 256] + aself * exer[e*KDIM + tid + 256];
    } else {
        float u0 = g_agg3p[0][e*KDIM + tid]       + g_agg3p[1][e*KDIM + tid]
                 + g_agg3p[2][e*KDIM + tid]       + g_agg3p[3][e*KDIM + tid];
        float u1 = g_agg3p[0][e*KDIM + tid + 256] + g_agg3p[1][e*KDIM + tid + 256]
                 + g_agg3p[2][e*KDIM + tid + 256] + g_agg3p[3][e*KDIM + tid + 256];
        srow[tid]       = u0*iden + aself * exer[e*KDIM + tid];
        srow[tid + 256] = u1*iden + aself * exer[e*KDIM + tid + 256];
    }
    __syncthreads();
    const float* Wb = Wg + (size_t)g*KDIM*KDIM;
    float acc0 = bg[g*KDIM + tid], acc1 = bg[g*KDIM + tid + 256];
    for (int i = 0; i < KDIM; i++){
        float s = srow[i];
        acc0 += s * Wb[i*KDIM + tid];
        acc1 += s * Wb[i*KDIM + tid + 256];
    }
    float* dst = isB ? g_B : g_C;
    dst[e*KDIM + tid] = acc0;
    dst[e*KDIM + tid + 256] = acc1;
    __syncthreads();
    if (threadIdx.x == 0) mark_done(&g_cbc);
}

__device__ void exer_body(char* dsm, const float* __restrict__ exer,
                          const float* __restrict__ aw, const float* __restrict__ ab,
                          float* __restrict__ outE)
{
    spin0(&g_cbc, NB_BC);
    float* red = (float*)dsm;
    int tid = threadIdx.x;
    for (int e = 0; e < EN; e++){
        float xv0 = exer[e*KDIM + tid],       xv1 = exer[e*KDIM + tid + 256];
        float bv0 = g_B[e*KDIM + tid],        bv1 = g_B[e*KDIM + tid + 256];
        float cv0 = g_C[e*KDIM + tid],        cv1 = g_C[e*KDIM + tid + 256];
        red[tid] = xv0*aw[1024 + tid]       + bv0*aw[1024 + KDIM + tid]
                 + xv1*aw[1024 + tid + 256] + bv1*aw[1024 + KDIM + tid + 256];
        __syncthreads();
        for (int o = 128; o; o >>= 1){ if (tid < o) red[tid] += red[tid+o]; __syncthreads(); }
        float s1 = red[0] + ab[1];
        __syncthreads();
        red[tid] = xv0*aw[2048 + tid]       + cv0*aw[2048 + KDIM + tid]
                 + xv1*aw[2048 + tid + 256] + cv1*aw[2048 + KDIM + tid + 256];
        __syncthreads();
        for (int o = 128; o; o >>= 1){ if (tid < o) red[tid] += red[tid+o]; __syncthreads(); }
        float s2 = red[0] + ab[2];
        __syncthreads();
        float mx = fmaxf(s1, s2);
        float e1 = expf(s1 - mx), e2 = expf(s2 - mx);
        float inv = 1.f / (e1 + e2);
        float w1 = e1*inv, w2 = e2*inv;
        outE[e*KDIM + tid]       = xv0 + w1*bv0 + w2*cv0;
        outE[e*KDIM + tid + 256] = xv1 + w1*bv1 + w2*cv1;
    }
    // reset launch-1 producer counter for the next graph replay
    __syncthreads();
    if (tid == 0){ __threadfence(); g_cA = 0; }
}

// Phase C: GEMM + agg1 + kn-GEMM + bc + exer, one launch
__global__ void __launch_bounds__(256, 2) k_phaseC(
    const int* __restrict__ eue, const int* __restrict__ eek,
    const int* __restrict__ eke, const float* __restrict__ kn,
    const float* __restrict__ Wg, const float* __restrict__ bg,
    const float* __restrict__ exer, const float* __restrict__ aw,
    const float* __restrict__ ab,
    float* __restrict__ out_st, float* __restrict__ out_kn,
    float* __restrict__ out_ex)
{
    extern __shared__ __align__(16) char dsm[];
    int b = blockIdx.x;
    if (b < NB_GEMM){
        gemm_body(dsm, b & 3, b >> 2, eue, bg, out_st);
    } else if (b < OFF_KNG){
        agg1_body(dsm, b - OFF_AGG1, eek, kn);
    } else if (b < OFF_BC){
        gemm_gat_body(dsm, b - OFF_KNG, kn, Wg, bg, eke, out_kn);
    } else if (b < OFF_EXER){
        bc_body(dsm, b - OFF_BC, Wg, bg, exer);
    } else {
        exer_body(dsm, exer, aw, ab, out_ex);
    }
}

// ---------------- launcher ----------------
extern "C" void kernel_launch(void* const* d_in, const int* in_sizes, int n_in,
                              void* d_out, int out_size){
    const float* kn   = (const float*)d_in[0];
    const float* exer = (const float*)d_in[1];
    const float* stu  = (const float*)d_in[2];
    const float* Wg   = (const float*)d_in[3];
    const float* a_s  = (const float*)d_in[4];
    const float* a_d  = (const float*)d_in[5];
    const float* bg   = (const float*)d_in[6];
    const float* aw   = (const float*)d_in[7];
    const float* ab   = (const float*)d_in[8];
    const int* eke    = (const int*)d_in[9];
    const int* eek    = (const int*)d_in[10];
    const int* eue    = (const int*)d_in[11];
    const int* eeu    = (const int*)d_in[12];
    (void)in_sizes; (void)n_in; (void)out_size;

    float* out    = (float*)d_out;
    float* out_kn = out;
    float* out_ex = out + KDIM*KDIM;
    float* out_st = out + KDIM*KDIM + EN*KDIM;

    static int s_attr_done = 0;
    if (!s_attr_done){
        cudaFuncSetAttribute(k_phaseC, cudaFuncAttributeMaxDynamicSharedMemorySize,
                             MMA_SMEM);
        s_attr_done = 1;
    }

    k_fuseAB<<<NB_L1, 512>>>(Wg, a_s, a_d, exer, stu, kn, eeu);
    k_phaseC<<<NB_C, 256, MMA_SMEM>>>(
        eue, eek, eke, kn, Wg, bg, exer, aw, ab, out_st, out_kn, out_ex);
}

// round 17
// speedup vs baseline: 1.7286x; 1.1974x over previous
#include <cuda_runtime.h>
#include <cuda_fp16.h>
#include <cstdint>

#define KDIM 512
#define S_N 50000
#define EN 6
#define NEG 0.2f
#define NE3 150000

// ---------------- scratch (static __device__, no allocation) ----------------
__device__ float g_wa[4][2][KDIM];      // W_g @ a_src / a_dst
__device__ float g_he[4][EN][KDIM];     // exer_emb @ W_g
__device__ float g_ase[4][EN];          // h_e . a_src
__device__ float g_ade[4][EN];          // h_e . a_dst
__device__ float g_as2[S_N], g_ad2[S_N], g_as3[S_N];
__device__ float g_as0[KDIM], g_ad0[KDIM], g_as1[KDIM];
__device__ float g_den1[EN], g_den3[EN];
__device__ float g_agg1[EN*KDIM];
__device__ float g_agg3[EN*KDIM];       // UN-normalized GAT3 aggregate
__device__ float g_w3[(size_t)S_N*EN];  // dense per-student GAT3 weight 6-vector
__device__ float g_B[EN*KDIM], g_C[EN*KDIM];
// counters: g_cA zeroed by phaseC's exer (prev replay) / static init;
// g_c1/g_c3/g_cbc zeroed by launch-1's init block (ordered before phaseC).
__device__ int g_cA, g_c1, g_c3, g_cbc;

// fp16 operands for the tensor-core student GEMM
__device__ __half g_Ah[(size_t)S_N*KDIM];
__device__ __half g_Wh[KDIM*KDIM];   // W2^T: [n][k]

__device__ __forceinline__ float lrelu(float x){ return x > 0.f ? x : NEG*x; }

// ---------------- PTX helpers (all legal on plain compute_103) ----------------
__device__ __forceinline__ uint32_t smem_u32(const void* p){
    uint32_t a;
    asm("{ .reg .u64 t; cvta.to.shared.u64 t, %1; cvt.u32.u64 %0, t; }" : "=r"(a) : "l"(p));
    return a;
}
__device__ __forceinline__ void cpa16(uint32_t s, const void* g){
    asm volatile("cp.async.cg.shared.global [%0], [%1], 16;" :: "r"(s), "l"(g));
}
#define CPA_COMMIT() asm volatile("cp.async.commit_group;" ::: "memory")
#define CPA_WAIT(n)  asm volatile("cp.async.wait_group %0;" :: "n"(n) : "memory")

__device__ __forceinline__ void ldsm4(uint32_t& r0, uint32_t& r1, uint32_t& r2, uint32_t& r3,
                                      uint32_t addr){
    asm volatile("ldmatrix.sync.aligned.m8n8.x4.shared.b16 {%0,%1,%2,%3}, [%4];"
                 : "=r"(r0), "=r"(r1), "=r"(r2), "=r"(r3) : "r"(addr));
}
__device__ __forceinline__ void mma_f16(float* c, const uint32_t* a, const uint32_t* b){
    asm volatile(
        "mma.sync.aligned.m16n8k16.row.col.f32.f16.f16.f32 "
        "{%0,%1,%2,%3}, {%4,%5,%6,%7}, {%8,%9}, {%0,%1,%2,%3};"
        : "+f"(c[0]), "+f"(c[1]), "+f"(c[2]), "+f"(c[3])
        : "r"(a[0]), "r"(a[1]), "r"(a[2]), "r"(a[3]), "r"(b[0]), "r"(b[1]));
}
__device__ __forceinline__ void spin_until(const int* p, int target){
    while (true){
        int v;
        asm volatile("ld.global.acquire.gpu.b32 %0, [%1];" : "=r"(v) : "l"(p));
        if (v >= target) break;
        __nanosleep(128);
    }
}
__device__ __forceinline__ void spin0(const int* p, int target){
    if (threadIdx.x == 0) spin_until(p, target);
    __syncthreads();
}
__device__ __forceinline__ void mark_done(int* p){
    __threadfence();
    atomicAdd(p, 1);
}

// =====================================================================
// Launch 1: fuseA producers + fb students + kn matvec, 512 thr
// =====================================================================
#define NPROD 33
#define FB0   97
#define NB_FB 3125
#define KN0   (FB0 + NB_FB)
#define NB_KNMV 32
#define NB_L1 (KN0 + NB_KNMV)

__global__ void __launch_bounds__(512) k_fuseAB(
    const float* __restrict__ Wg, const float* __restrict__ a_src,
    const float* __restrict__ a_dst, const float* __restrict__ exer,
    const float* __restrict__ stu, const float* __restrict__ kn,
    const int* __restrict__ eeu)
{
    __shared__ float sv[KDIM];
    __shared__ float red[KDIM];
    __shared__ float tile[64][65];
    __shared__ float s0[KDIM], s1[KDIM], s2[KDIM];
    __shared__ float sden[EN];
    __shared__ float sw6[16][EN];
    int b = blockIdx.x, tid = threadIdx.x;
    int warp = tid >> 5, lane = tid & 31;

    if (b < 8) {
        int g = b >> 1, w = b & 1;
        const float* a = (w ? a_dst : a_src) + g*KDIM;
        sv[tid] = a[tid];
        __syncthreads();
        const float* Wb = Wg + (size_t)g*KDIM*KDIM;
        for (int r = warp; r < KDIM; r += 16) {
            float s = 0.f;
            for (int c = lane; c < KDIM; c += 32) s += Wb[r*KDIM + c] * sv[c];
            for (int o = 16; o; o >>= 1) s += __shfl_down_sync(0xffffffffu, s, o);
            if (lane == 0) g_wa[g][w][r] = s;
        }
        __syncthreads();
        if (tid == 0) mark_done(&g_cA);
    } else if (b < 32) {
        int t = b - 8, g = t / EN, j = t % EN;
        sv[tid] = exer[j*KDIM + tid];
        __syncthreads();
        const float* Wb = Wg + (size_t)g*KDIM*KDIM;
        float acc = 0.f;
        for (int i = 0; i < KDIM; i++) acc += sv[i] * Wb[i*KDIM + tid];
        g_he[g][j][tid] = acc;
        red[tid] = acc * a_src[g*KDIM + tid];
        __syncthreads();
        for (int o = 256; o; o >>= 1){ if (tid < o) red[tid] += red[tid+o]; __syncthreads(); }
        if (tid == 0) g_ase[g][j] = red[0];
        __syncthreads();
        red[tid] = acc * a_dst[g*KDIM + tid];
        __syncthreads();
        for (int o = 256; o; o >>= 1){ if (tid < o) red[tid] += red[tid+o]; __syncthreads(); }
        if (tid == 0){ g_ade[g][j] = red[0]; mark_done(&g_cA); }
    } else if (b < 96) {
        // coalesced 64x64 tile transpose of W2 into g_Wh (fp16); phaseC-only
        int t = b - 32;
        int row0 = (t >> 3)*64, col0 = (t & 7)*64;
        const float* W2 = Wg + 2*KDIM*KDIM;
        for (int i = tid; i < 4096; i += 512){
            int r = i >> 6, c = i & 63;
            tile[r][c] = W2[(size_t)(row0 + r)*KDIM + col0 + c];
        }
        __syncthreads();
        for (int i = tid; i < 4096; i += 512){
            int n = i >> 6, k = i & 63;
            g_Wh[(size_t)(col0 + n)*KDIM + row0 + k] = __float2half_rn(tile[k][n]);
        }
    } else if (b == 96) {
        if (tid < EN) g_den3[tid] = 0.f;
        if (tid == 511){ g_c1 = 0; g_c3 = 0; g_cbc = 0; }
        for (int i = tid; i < EN*KDIM; i += 512){ g_agg1[i] = 0.f; g_agg3[i] = 0.f; }
        __syncthreads();
        if (tid == 0) mark_done(&g_cA);
    } else if (b < KN0) {
        // fb students: fp16 convert + 3-way matvec + den3 + dense w3 vector
        spin0(&g_cA, NPROD);
        int idx = b - FB0;
        for (int i = tid; i < KDIM; i += 512){
            s0[i] = g_wa[2][0][i]; s1[i] = g_wa[2][1][i]; s2[i] = g_wa[3][0][i];
        }
        if (tid < EN) sden[tid] = 0.f;
        if (tid < 16*EN) sw6[tid / EN][tid % EN] = 0.f;
        __syncthreads();
        if (idx == 0 && tid < EN)
            atomicAdd(&g_den3[tid], expf(lrelu(g_ase[3][tid] + g_ade[3][tid])));
        int row = idx*16 + warp;
        const float4* xr = (const float4*)(stu + (size_t)row*KDIM);
        __half2* h2 = (__half2*)(g_Ah + (size_t)row*KDIM);
        float a0 = 0.f, a1 = 0.f, a2 = 0.f;
        #pragma unroll
        for (int i = 0; i < 4; i++){
            int q = lane + 32*i;
            float4 f = xr[q];
            int c = 4*q;
            a0 += f.x*s0[c] + f.y*s0[c+1] + f.z*s0[c+2] + f.w*s0[c+3];
            a1 += f.x*s1[c] + f.y*s1[c+1] + f.z*s1[c+2] + f.w*s1[c+3];
            a2 += f.x*s2[c] + f.y*s2[c+1] + f.z*s2[c+2] + f.w*s2[c+3];
            h2[2*q]   = __floats2half2_rn(f.x, f.y);
            h2[2*q+1] = __floats2half2_rn(f.z, f.w);
        }
        for (int o = 16; o; o >>= 1){
            a0 += __shfl_down_sync(0xffffffffu, a0, o);
            a1 += __shfl_down_sync(0xffffffffu, a1, o);
            a2 += __shfl_down_sync(0xffffffffu, a2, o);
        }
        if (lane == 0){
            g_as2[row] = a0; g_ad2[row] = a1; g_as3[row] = a2;
            #pragma unroll
            for (int j = 0; j < 3; j++){
                int d = eeu[NE3 + 3*row + j];
                float w = expf(lrelu(a2 + g_ade[3][d]));
                atomicAdd(&sden[d], w);
                atomicAdd(&sw6[warp][d], w);   // 3 smem atomics per row, trivial
            }
        }
        __syncthreads();
        if (tid < 16*EN)
            g_w3[(size_t)(idx*16 + tid / EN)*EN + (tid % EN)] = sw6[tid / EN][tid % EN];
        if (tid < EN && sden[tid] != 0.f) atomicAdd(&g_den3[tid], sden[tid]);
    } else {
        // kn 3-way matvec
        spin0(&g_cA, NPROD);
        int idx = b - KN0;
        for (int i = tid; i < KDIM; i += 512){
            s0[i] = g_wa[0][0][i]; s1[i] = g_wa[0][1][i]; s2[i] = g_wa[1][0][i];
        }
        __syncthreads();
        int row = idx*16 + warp;
        float a0 = 0.f, a1 = 0.f, a2 = 0.f;
        const float* xr = kn + (size_t)row*KDIM;
        for (int c = lane; c < KDIM; c += 32){
            float v = xr[c]; a0 += v*s0[c]; a1 += v*s1[c]; a2 += v*s2[c];
        }
        for (int o = 16; o; o >>= 1){
            a0 += __shfl_down_sync(0xffffffffu, a0, o);
            a1 += __shfl_down_sync(0xffffffffu, a1, o);
            a2 += __shfl_down_sync(0xffffffffu, a2, o);
        }
        if (lane == 0){ g_as0[row] = a0; g_ad0[row] = a1; g_as1[row] = a2; }
    }
}

// =====================================================================
// Phase C bodies
// =====================================================================
#define A_STG 10240
#define STG   20480
#define RING  (4*STG)                          // 81920
#define MMA_SMEM (RING + (EN*128 + 128 + 8)*4)

#define NB_GEMM 1564
#define NB_AGG3 782
#define NB_AGG1 8
#define NB_KN   16
#define NB_BC   12
#define NB_EXER 1
#define OFF_AGG3 (NB_GEMM)
#define OFF_AGG1 (OFF_AGG3 + NB_AGG3)
#define OFF_KNG  (OFF_AGG1 + NB_AGG1)
#define OFF_BC   (OFF_KNG + NB_KN)
#define OFF_EXER (OFF_BC + NB_BC)
#define NB_C     (OFF_EXER + NB_EXER)

// ---- student GEMM with fused GAT2 epilogue ----
__device__ __forceinline__ void gemm_body(
    char* dsm, int bx, int by, const int* __restrict__ esrc,
    const float* __restrict__ bg, float* __restrict__ out)
{
    float* he_s  = (float*)(dsm + RING);
    float* b_s   = he_s + EN*128;
    float* ase_s = b_s + 128;

    const uint32_t sb = smem_u32(dsm);
    int tid = threadIdx.x, lane = tid & 31, wid = tid >> 5;
    int mBase = by * 128, nBase = bx * 128;

    for (int i = tid; i < EN*128; i += 256)
        he_s[i] = g_he[2][i >> 7][nBase + (i & 127)];
    if (tid < 128) b_s[tid] = bg[2*KDIM + nBase + tid];
    if (tid < EN) ase_s[tid] = g_ase[2][tid];

    const char* gA = (const char*)g_Ah;
    const char* gW = (const char*)g_Wh;

    auto load_stage = [&](int s, int chunk){
        uint32_t base = sb + s*STG;
        int kB = chunk*64;
        #pragma unroll
        for (int u = tid; u < 512; u += 256){
            int rowi = u >> 2, cc = u & 3;
            uint32_t dst = (uint32_t)(rowi*80 + cc*16);
            int gr = mBase + rowi; if (gr >= S_N) gr = S_N - 1;
            cpa16(base + dst,          gA + (size_t)gr*(KDIM*2) + kB + cc*16);
            cpa16(base + A_STG + dst,  gW + (size_t)(nBase + rowi)*(KDIM*2) + kB + cc*16);
        }
    };

    float acc[2][8][4];
    #pragma unroll
    for (int a = 0; a < 2; a++)
        #pragma unroll
        for (int b2 = 0; b2 < 8; b2++)
            #pragma unroll
            for (int c = 0; c < 4; c++) acc[a][b2][c] = 0.f;

    int wm = (wid & 3) * 32;
    int wn = (wid >> 2) * 64;
    uint32_t aOff = (uint32_t)((lane & 15)*80 + (lane >> 4)*16);
    uint32_t bOff = (uint32_t)(((lane & 7) + ((lane >> 4) << 3))*80 + (((lane >> 3) & 1) << 4));

    load_stage(0, 0); CPA_COMMIT();
    load_stage(1, 1); CPA_COMMIT();
    load_stage(2, 2); CPA_COMMIT();

    for (int c = 0; c < 16; c++){
        if (c < 14){ CPA_WAIT(2); }
        else if (c == 14){ CPA_WAIT(1); }
        else { CPA_WAIT(0); }
        __syncthreads();
        if (c < 13){ load_stage((c + 3) & 3, c + 3); CPA_COMMIT(); }

        uint32_t base = sb + (c & 3)*STG;
        uint32_t aB = base + wm*80 + aOff;
        uint32_t bB = base + A_STG + wn*80 + bOff;

        #pragma unroll
        for (int ks = 0; ks < 2; ks++){
            uint32_t ah[2][4], bh[16];
            #pragma unroll
            for (int mf = 0; mf < 2; mf++)
                ldsm4(ah[mf][0], ah[mf][1], ah[mf][2], ah[mf][3],
                      aB + mf*16*80 + ks*32);
            #pragma unroll
            for (int p = 0; p < 4; p++)
                ldsm4(bh[p*4+0], bh[p*4+1], bh[p*4+2], bh[p*4+3],
                      bB + p*16*80 + ks*32);
            #pragma unroll
            for (int mf = 0; mf < 2; mf++)
                #pragma unroll
                for (int nf = 0; nf < 8; nf++)
                    mma_f16(acc[mf][nf], ah[mf], &bh[nf*2]);
        }
    }

    #pragma unroll
    for (int mf = 0; mf < 2; mf++){
        #pragma unroll
        for (int half = 0; half < 2; half++){
            int row = mBase + wm + mf*16 + (lane >> 2) + half*8;
            bool ok = row < S_N;
            int rr = ok ? row : S_N - 1;
            float adv = g_ad2[rr], asv = g_as2[rr];
            float eself = lrelu(asv + adv);
            int e0 = esrc[rr*3], e1 = esrc[rr*3 + 1], e2 = esrc[rr*3 + 2];
            float v0 = lrelu(ase_s[e0] + adv);
            float v1 = lrelu(ase_s[e1] + adv);
            float v2 = lrelu(ase_s[e2] + adv);
            float mx = fmaxf(fmaxf(eself, v0), fmaxf(v1, v2));
            float aS = expf(eself - mx), a0 = expf(v0 - mx);
            float a1 = expf(v1 - mx),  a2 = expf(v2 - mx);
            float inv = 1.f / (aS + a0 + a1 + a2);
            aS *= inv; a0 *= inv; a1 *= inv; a2 *= inv;
            #pragma unroll
            for (int nf = 0; nf < 8; nf++){
                int cl = wn + nf*8 + (lane & 3)*2;
                int col = nBase + cl;
                float2 xv = __half22float2(
                    *(const __half2*)(g_Ah + (size_t)rr*KDIM + col));
                #pragma unroll
                for (int j = 0; j < 2; j++){
                    float v = (j ? xv.y : xv.x) + b_s[cl + j]
                            + aS*acc[mf][nf][half*2 + j]
                            + a0*he_s[e0*128 + cl + j] + a1*he_s[e1*128 + cl + j]
                            + a2*he_s[e2*128 + cl + j];
                    if (ok) out[(size_t)row*KDIM + col + j] = v;
                }
            }
        }
    }
}

// ---- GAT3 aggregation: dense rank-6 register accumulation, atomic-free loop ----
__device__ void gat3_agg_body(char* dsm, int idx)
{
    float* sw = (float*)dsm;                 // [64][6]
    int tid = threadIdx.x;
    int base = idx*64;
    for (int i = tid; i < 64*EN; i += 256)
        sw[i] = g_w3[(size_t)(base + (i / EN))*EN + (i % EN)];
    __syncthreads();

    float acc[EN][2];
    #pragma unroll
    for (int e = 0; e < EN; e++){ acc[e][0] = 0.f; acc[e][1] = 0.f; }

    const __half2* A2 = (const __half2*)g_Ah;
    for (int sl = 0; sl < 64; sl++){
        float2 x = __half22float2(A2[(size_t)(base + sl)*256 + tid]);
        const float* w = &sw[sl*EN];
        #pragma unroll
        for (int e = 0; e < EN; e++){
            acc[e][0] += w[e]*x.x;
            acc[e][1] += w[e]*x.y;
        }
    }
    #pragma unroll
    for (int e = 0; e < EN; e++){
        atomicAdd(&g_agg3[e*KDIM + 2*tid],     acc[e][0]);
        atomicAdd(&g_agg3[e*KDIM + 2*tid + 1], acc[e][1]);
    }
    __syncthreads();
    if (tid == 0) mark_done(&g_c3);
}

__device__ void agg1_body(char* dsm, int idx, const int* __restrict__ ek,
                          const float* __restrict__ kn)
{
    float* sagg = (float*)dsm;
    float* sal  = sagg + EN*KDIM;
    int*   sd   = (int*)(sal + 256);
    int*   ss   = sd + 256;
    float* sden = (float*)(ss + 256);
    int tid = threadIdx.x;
    for (int i = tid; i < EN*KDIM; i += 256) sagg[i] = 0.f;
    if (tid < EN) sden[tid] = expf(lrelu(g_ase[1][tid] + g_ade[1][tid]));
    __syncthreads();
    for (int t = tid; t < 2048; t += 256){
        int k = ek[t] - EN, d = ek[2048 + t];
        atomicAdd(&sden[d], expf(lrelu(g_as1[k] + g_ade[1][d])));
    }
    __syncthreads();
    int t = idx*256 + tid;
    {
        int k = ek[t] - EN, d = ek[2048 + t];
        sal[tid] = expf(lrelu(g_as1[k] + g_ade[1][d])) / sden[d];
        sd[tid] = d; ss[tid] = k;
    }
    if (idx == 0 && tid < EN) g_den1[tid] = sden[tid];
    __syncthreads();
    for (int el = 0; el < 256; el++){
        int d = sd[el]; float al = sal[el];
        const float* kr = kn + (size_t)ss[el]*KDIM;
        sagg[d*KDIM + tid]       += al*kr[tid];
        sagg[d*KDIM + 256 + tid] += al*kr[256 + tid];
    }
    __syncthreads();
    for (int i = tid; i < EN*KDIM; i += 256) atomicAdd(&g_agg1[i], sagg[i]);
    __syncthreads();
    if (tid == 0) mark_done(&g_c1);
}

__device__ void gemm_gat_body(char* dsm, int idx,
                              const float* __restrict__ A, const float* __restrict__ W,
                              const float* __restrict__ b, const int* __restrict__ esrc,
                              float* __restrict__ out)
{
    float (*As)[128] = (float(*)[128])dsm;
    float (*Bs)[128] = (float(*)[128])(dsm + 4096);
    float* he_s  = (float*)(dsm + 8192);
    float* b_s   = he_s + EN*128;
    float* ase_s = b_s + 128;
    int tid = threadIdx.x;
    int tx = tid & 15, ty = tid >> 4;
    int colBase = (idx & 3)*128, rowBase = (idx >> 2)*128;

    if (tid < 128) b_s[tid] = b[colBase + tid];
    if (tid >= 128 && tid < 128 + EN) ase_s[tid - 128] = g_ase[0][tid - 128];
    for (int i = tid; i < EN*128; i += 256)
        he_s[i] = g_he[0][i >> 7][colBase + (i & 127)];

    int aRow = tid >> 1, aCol = (tid & 1)*4;
    int bRow = tid >> 5, bCol = (tid & 31)*4;
    const float* Aptr = A + (size_t)(rowBase + aRow)*KDIM + aCol;
    const float* Wptr = W + (size_t)bRow*KDIM + colBase + bCol;

    float acc[8][8];
    #pragma unroll
    for (int i = 0; i < 8; i++)
        #pragma unroll
        for (int j = 0; j < 8; j++) acc[i][j] = 0.f;

    for (int k0 = 0; k0 < KDIM; k0 += 8){
        float4 av = *(const float4*)(Aptr + k0);
        float4 wv = *(const float4*)(Wptr + (size_t)k0*KDIM);
        __syncthreads();
        As[aCol+0][aRow] = av.x; As[aCol+1][aRow] = av.y;
        As[aCol+2][aRow] = av.z; As[aCol+3][aRow] = av.w;
        *(float4*)&Bs[bRow][bCol] = wv;
        __syncthreads();
        #pragma unroll
        for (int kk = 0; kk < 8; kk++){
            float4 a0 = *(const float4*)&As[kk][ty*8];
            float4 a1 = *(const float4*)&As[kk][ty*8 + 4];
            float4 b0 = *(const float4*)&Bs[kk][tx*8];
            float4 b1 = *(const float4*)&Bs[kk][tx*8 + 4];
            float ar[8] = {a0.x,a0.y,a0.z,a0.w,a1.x,a1.y,a1.z,a1.w};
            float br[8] = {b0.x,b0.y,b0.z,b0.w,b1.x,b1.y,b1.z,b1.w};
            #pragma unroll
            for (int i = 0; i < 8; i++)
                #pragma unroll
                for (int j = 0; j < 8; j++)
                    acc[i][j] += ar[i]*br[j];
        }
    }

    #pragma unroll
    for (int i = 0; i < 8; i++){
        int row = rowBase + ty*8 + i;
        float asv = g_as0[row], adv = g_ad0[row];
        float eself = lrelu(asv + adv);
        float mx = eself;
        int srcs[4]; float ev[4];
        #pragma unroll
        for (int j = 0; j < 4; j++){
            int s = esrc[row*4 + j];
            srcs[j] = s;
            float e = lrelu(ase_s[s] + adv);
            ev[j] = e; mx = fmaxf(mx, e);
        }
        float aself = expf(eself - mx);
        float se = aself;
        float al[4];
        #pragma unroll
        for (int j = 0; j < 4; j++){ al[j] = expf(ev[j] - mx); se += al[j]; }
        float inv = 1.f / se;
        aself *= inv;
        #pragma unroll
        for (int j = 0; j < 4; j++) al[j] *= inv;

        const float* xr = A + (size_t)row*KDIM + colBase;
        float* orow = out + (size_t)row*KDIM + colBase;
        #pragma unroll
        for (int jj = 0; jj < 8; jj++){
            int c = tx*8 + jj;
            float v = xr[c] + b_s[c] + aself*acc[i][jj];
            #pragma unroll
            for (int j = 0; j < 4; j++) v += al[j]*he_s[srcs[j]*128 + c];
            orow[c] = v;
        }
    }
}

__device__ void bc_body(char* dsm, int r, const float* __restrict__ Wg,
                        const float* __restrict__ bg, const float* __restrict__ exer)
{
    if (threadIdx.x == 0){ spin_until(&g_c1, NB_AGG1); spin_until(&g_c3, NB_AGG3); }
    __syncthreads();
    float* srow = (float*)dsm;
    int tid = threadIdx.x;
    int isB = (r < EN) ? 1 : 0;
    int e = isB ? r : r - EN;
    int g = isB ? 1 : 3;
    float den = isB ? g_den1[e] : g_den3[e];
    float iden = 1.f / den;
    float aself = expf(lrelu(g_ase[g][e] + g_ade[g][e])) * iden;
    if (isB){
        srow[tid]       = g_agg1[e*KDIM + tid]       + aself * exer[e*KDIM + tid];
        srow[tid + 256] = g_agg1[e*KDIM + tid + 256] + aself * exer[e*KDIM + tid + 256];
    } else {
        srow[tid]       = g_agg3[e*KDIM + tid]*iden       + aself * exer[e*KDIM + tid];
        srow[tid + 256] = g_agg3[e*KDIM + tid + 256]*iden + aself * exer[e*KDIM + tid + 256];
    }
    __syncthreads();
    const float* Wb = Wg + (size_t)g*KDIM*KDIM;
    float acc0 = bg[g*KDIM + tid], acc1 = bg[g*KDIM + tid + 256];
    for (int i = 0; i < KDIM; i++){
        float s = srow[i];
        acc0 += s * Wb[i*KDIM + tid];
        acc1 += s * Wb[i*KDIM + tid + 256];
    }
    float* dst = isB ? g_B : g_C;
    dst[e*KDIM + tid] = acc0;
    dst[e*KDIM + tid + 256] = acc1;
    __syncthreads();
    if (threadIdx.x == 0) mark_done(&g_cbc);
}

__device__ void exer_body(char* dsm, const float* __restrict__ exer,
                          const float* __restrict__ aw, const float* __restrict__ ab,
                          float* __restrict__ outE)
{
    spin0(&g_cbc, NB_BC);
    float* red = (float*)dsm;
    int tid = threadIdx.x;
    for (int e = 0; e < EN; e++){
        float xv0 = exer[e*KDIM + tid],       xv1 = exer[e*KDIM + tid + 256];
        float bv0 = g_B[e*KDIM + tid],        bv1 = g_B[e*KDIM + tid + 256];
        float cv0 = g_C[e*KDIM + tid],        cv1 = g_C[e*KDIM + tid + 256];
        red[tid] = xv0*aw[1024 + tid]       + bv0*aw[1024 + KDIM + tid]
                 + xv1*aw[1024 + tid + 256] + bv1*aw[1024 + KDIM + tid + 256];
        __syncthreads();
        for (int o = 128; o; o >>= 1){ if (tid < o) red[tid] += red[tid+o]; __syncthreads(); }
        float s1 = red[0] + ab[1];
        __syncthreads();
        red[tid] = xv0*aw[2048 + tid]       + cv0*aw[2048 + KDIM + tid]
                 + xv1*aw[2048 + tid + 256] + cv1*aw[2048 + KDIM + tid + 256];
        __syncthreads();
        for (int o = 128; o; o >>= 1){ if (tid < o) red[tid] += red[tid+o]; __syncthreads(); }
        float s2 = red[0] + ab[2];
        __syncthreads();
        float mx = fmaxf(s1, s2);
        float e1 = expf(s1 - mx), e2 = expf(s2 - mx);
        float inv = 1.f / (e1 + e2);
        float w1 = e1*inv, w2 = e2*inv;
        outE[e*KDIM + tid]       = xv0 + w1*bv0 + w2*cv0;
        outE[e*KDIM + tid + 256] = xv1 + w1*bv1 + w2*cv1;
    }
    // reset launch-1 producer counter for the next graph replay
    __syncthreads();
    if (tid == 0){ __threadfence(); g_cA = 0; }
}

// Phase C: GEMM + agg3 + agg1 + kn-GEMM + bc + exer, one launch
__global__ void __launch_bounds__(256, 2) k_phaseC(
    const int* __restrict__ eue, const int* __restrict__ eek,
    const int* __restrict__ eke, const float* __restrict__ kn,
    const float* __restrict__ Wg, const float* __restrict__ bg,
    const float* __restrict__ exer, const float* __restrict__ aw,
    const float* __restrict__ ab,
    float* __restrict__ out_st, float* __restrict__ out_kn,
    float* __restrict__ out_ex)
{
    extern __shared__ __align__(16) char dsm[];
    int b = blockIdx.x;
    if (b < NB_GEMM){
        gemm_body(dsm, b & 3, b >> 2, eue, bg, out_st);
    } else if (b < OFF_AGG1){
        gat3_agg_body(dsm, b - OFF_AGG3);
    } else if (b < OFF_KNG){
        agg1_body(dsm, b - OFF_AGG1, eek, kn);
    } else if (b < OFF_BC){
        gemm_gat_body(dsm, b - OFF_KNG, kn, Wg, bg, eke, out_kn);
    } else if (b < OFF_EXER){
        bc_body(dsm, b - OFF_BC, Wg, bg, exer);
    } else {
        exer_body(dsm, exer, aw, ab, out_ex);
    }
}

// ---------------- launcher ----------------
extern "C" void kernel_launch(void* const* d_in, const int* in_sizes, int n_in,
                              void* d_out, int out_size){
    const float* kn   = (const float*)d_in[0];
    const float* exer = (const float*)d_in[1];
    const float* stu  = (const float*)d_in[2];
    const float* Wg   = (const float*)d_in[3];
    const float* a_s  = (const float*)d_in[4];
    const float* a_d  = (const float*)d_in[5];
    const float* bg   = (const float*)d_in[6];
    const float* aw   = (const float*)d_in[7];
    const float* ab   = (const float*)d_in[8];
    const int* eke    = (const int*)d_in[9];
    const int* eek    = (const int*)d_in[10];
    const int* eue    = (const int*)d_in[11];
    const int* eeu    = (const int*)d_in[12];
    (void)in_sizes; (void)n_in; (void)out_size;

    float* out    = (float*)d_out;
    float* out_kn = out;
    float* out_ex = out + KDIM*KDIM;
    float* out_st = out + KDIM*KDIM + EN*KDIM;

    static int s_attr_done = 0;
    if (!s_attr_done){
        cudaFuncSetAttribute(k_phaseC, cudaFuncAttributeMaxDynamicSharedMemorySize,
                             MMA_SMEM);
        s_attr_done = 1;
    }

    k_fuseAB<<<NB_L1, 512>>>(Wg, a_s, a_d, exer, stu, kn, eeu);
    k_phaseC<<<NB_C, 256, MMA_SMEM>>>(
        eue, eek, eke, kn, Wg, bg, exer, aw, ab, out_st, out_kn, out_ex);
}